// round 1
// baseline (speedup 1.0000x reference)
#include <cuda_runtime.h>
#include <math_constants.h>

#define NM 1024
#define HGT 256
#define WID 256
#define HW 65536

#define MASK_THR 0.0f
#define STAB_OFF 1.0f
#define IOU_THR 0.88f
#define STAB_THR 0.95f
#define NMS_THR 0.7f

// Scratch (static device globals -- no runtime allocation)
__device__ int g_hi[NM];
__device__ int g_lo[NM];
__device__ int4 g_box[NM];            // left, top, right, bottom (ints; bottom=-1 => empty)
__device__ float g_gated[NM];
__device__ unsigned g_supmask[NM * 32];

// ---------------------------------------------------------------------------
// Kernel 1: per-mask stats. One block per mask, 8 warps, warp-per-row sweep.
// Each warp handles 32 rows; per row a warp loads 64 float4 (coalesced 512B
// chunks), tracks hi/lo counts and binary-pixel x extents.
// ---------------------------------------------------------------------------
__global__ __launch_bounds__(256) void stats_kernel(const float* __restrict__ logits) {
    const int n = blockIdx.x;
    const int warp = threadIdx.x >> 5;
    const int lane = threadIdx.x & 31;
    const float* base = logits + (size_t)n * HW;

    int hi = 0, lo = 0;
    int left = WID, right = -1, top = HGT, bot = -1;

    for (int r = 0; r < 32; r++) {
        const int y = warp * 32 + r;
        const float4* row = reinterpret_cast<const float4*>(base + (size_t)y * WID);
        float4 a = row[lane];
        float4 b = row[lane + 32];

        int rxmin = WID, rxmax = -1;
        float va[8] = {a.x, a.y, a.z, a.w, b.x, b.y, b.z, b.w};
        #pragma unroll
        for (int c = 0; c < 8; c++) {
            float f = va[c];
            int x = (c < 4) ? (lane * 4 + c) : (lane * 4 + 128 + (c - 4));
            hi += (f > (MASK_THR + STAB_OFF)) ? 1 : 0;
            lo += (f > (MASK_THR - STAB_OFF)) ? 1 : 0;
            if (f > MASK_THR) {
                rxmin = min(rxmin, x);
                rxmax = max(rxmax, x);
            }
        }
        #pragma unroll
        for (int o = 16; o; o >>= 1) {
            rxmin = min(rxmin, __shfl_xor_sync(0xffffffffu, rxmin, o));
            rxmax = max(rxmax, __shfl_xor_sync(0xffffffffu, rxmax, o));
        }
        if (rxmax >= 0) {
            left  = min(left, rxmin);
            right = max(right, rxmax);
            top   = min(top, y);
            bot   = max(bot, y);
        }
    }

    // Warp-level butterfly reduction of accumulators.
    #pragma unroll
    for (int o = 16; o; o >>= 1) {
        hi   += __shfl_xor_sync(0xffffffffu, hi, o);
        lo   += __shfl_xor_sync(0xffffffffu, lo, o);
        left  = min(left,  __shfl_xor_sync(0xffffffffu, left, o));
        right = max(right, __shfl_xor_sync(0xffffffffu, right, o));
        top   = min(top,   __shfl_xor_sync(0xffffffffu, top, o));
        bot   = max(bot,   __shfl_xor_sync(0xffffffffu, bot, o));
    }

    __shared__ int s[8][6];
    if (lane == 0) {
        s[warp][0] = hi; s[warp][1] = lo;
        s[warp][2] = left; s[warp][3] = right;
        s[warp][4] = top; s[warp][5] = bot;
    }
    __syncthreads();
    if (threadIdx.x == 0) {
        int Hi = 0, Lo = 0, L = WID, R = -1, T = HGT, B = -1;
        #pragma unroll
        for (int w = 0; w < 8; w++) {
            Hi += s[w][0]; Lo += s[w][1];
            L = min(L, s[w][2]); R = max(R, s[w][3]);
            T = min(T, s[w][4]); B = max(B, s[w][5]);
        }
        g_hi[n] = Hi;
        g_lo[n] = Lo;
        g_box[n] = make_int4(L, T, R, B);
    }
}

// ---------------------------------------------------------------------------
// Kernel 2: validity + exact greedy NMS (matches jax argsort-stable ordering),
// writes keep + boxes tail of the output and gated scores for pass 3.
// Single block of 1024 threads.
// ---------------------------------------------------------------------------
__global__ __launch_bounds__(1024) void nms_kernel(const float* __restrict__ iou,
                                                   float* __restrict__ out_tail) {
    const int tid = threadIdx.x;
    __shared__ float s_score[NM];
    __shared__ float4 s_bx[NM];
    __shared__ int s_sorted[NM];
    __shared__ unsigned char s_keep[NM];

    float myiou = iou[tid];
    int4 b = g_box[tid];
    bool nonempty = (b.w >= 0);
    float4 bf = nonempty
        ? make_float4((float)b.x, (float)b.y, (float)b.z, (float)b.w)
        : make_float4(0.f, 0.f, 0.f, 0.f);
    s_bx[tid] = bf;

    float hi = (float)g_hi[tid];
    float lo = fmaxf((float)g_lo[tid], 1.0f);
    float stab = hi / lo;
    bool valid = (myiou > IOU_THR) && (stab >= STAB_THR);
    s_score[tid] = valid ? myiou : -CUDART_INF_F;
    s_keep[tid] = 0;
    int M = __syncthreads_count(valid);

    // Stable rank: score desc, ties -> lower original index first (jnp.argsort).
    if (valid) {
        float si = s_score[tid];
        int r = 0;
        for (int j = 0; j < NM; j++) {
            float sj = s_score[j];
            r += ((sj > si) || (sj == si && j < tid)) ? 1 : 0;
        }
        s_sorted[r] = tid;
    }
    __syncthreads();

    // Suppression bitmask: row i = sorted box i vs all sorted boxes (32 words).
    float4 mb = (tid < M) ? s_bx[s_sorted[tid]] : make_float4(0.f, 0.f, 0.f, 0.f);
    float areaB = fmaxf(mb.z - mb.x, 0.f) * fmaxf(mb.w - mb.y, 0.f);
    for (int i = 0; i < M; i++) {
        float4 ib = s_bx[s_sorted[i]];
        float areaA = fmaxf(ib.z - ib.x, 0.f) * fmaxf(ib.w - ib.y, 0.f);
        float ix = fmaxf(fminf(ib.z, mb.z) - fmaxf(ib.x, mb.x), 0.f);
        float iy = fmaxf(fminf(ib.w, mb.w) - fmaxf(ib.y, mb.y), 0.f);
        float inter = ix * iy;
        float iouv = inter / fmaxf(areaA + areaB - inter, 1e-6f);
        bool bit = (tid < M) && (iouv > NMS_THR);
        unsigned ball = __ballot_sync(0xffffffffu, bit);
        if ((tid & 31) == 0) g_supmask[i * 32 + (tid >> 5)] = ball;
    }
    __syncthreads();  // also fences the global supmask writes block-wide

    // Single-warp greedy over the bitmask (lane l owns removal word l).
    if (tid < 32) {
        unsigned removed = 0;
        for (int i = 0; i < M; i++) {
            unsigned wrd = __shfl_sync(0xffffffffu, removed, i >> 5);
            bool rem = (wrd >> (i & 31)) & 1u;
            if (!rem) {
                removed |= g_supmask[i * 32 + tid];
                if (tid == 0) s_keep[s_sorted[i]] = 1;
            }
        }
    }
    __syncthreads();

    bool kp = (s_keep[tid] != 0);
    g_gated[tid] = kp ? myiou : 0.f;
    out_tail[tid] = kp ? 1.f : 0.f;            // keep[N] as float
    float* ob = out_tail + NM + (size_t)tid * 4;  // boxes [N,4] = (x0,y0,x1,y1)
    ob[0] = bf.x; ob[1] = bf.y; ob[2] = bf.z; ob[3] = bf.w;
}

// ---------------------------------------------------------------------------
// Kernel 3: out = sigmoid(logits) * gated[n]. Suppressed masks are pure
// zero-fill (no load). Grid: (HW/4/256, NM), float4 per thread.
// ---------------------------------------------------------------------------
__global__ __launch_bounds__(256) void out_kernel(const float* __restrict__ logits,
                                                  float* __restrict__ out) {
    const int n = blockIdx.y;
    const float g = g_gated[n];
    const size_t base = (size_t)n * HW;
    const int idx = blockIdx.x * blockDim.x + threadIdx.x;
    float4* o4 = reinterpret_cast<float4*>(out + base);
    if (g == 0.f) {
        o4[idx] = make_float4(0.f, 0.f, 0.f, 0.f);
        return;
    }
    const float4* i4 = reinterpret_cast<const float4*>(logits + base);
    float4 v = i4[idx];
    v.x = __fdividef(g, 1.f + __expf(-v.x));
    v.y = __fdividef(g, 1.f + __expf(-v.y));
    v.z = __fdividef(g, 1.f + __expf(-v.z));
    v.w = __fdividef(g, 1.f + __expf(-v.w));
    o4[idx] = v;
}

extern "C" void kernel_launch(void* const* d_in, const int* in_sizes, int n_in,
                              void* d_out, int out_size) {
    const float* logits = (const float*)d_in[0];
    const float* iou = (const float*)d_in[1];
    if (n_in >= 2 && in_sizes[0] == NM && in_sizes[1] == NM * HW) {
        // Defensive against input-order swap.
        logits = (const float*)d_in[1];
        iou = (const float*)d_in[0];
    }
    float* out = (float*)d_out;

    stats_kernel<<<NM, 256>>>(logits);
    nms_kernel<<<1, NM>>>(iou, out + (size_t)NM * HW);
    dim3 grid(HW / 4 / 256, NM);
    out_kernel<<<grid, 256>>>(logits, out);
}

// round 2
// speedup vs baseline: 1.0554x; 1.0554x over previous
#include <cuda_runtime.h>
#include <math_constants.h>

#define NM 1024
#define HGT 256
#define WID 256
#define HW 65536

#define MASK_THR 0.0f
#define STAB_OFF 1.0f
#define IOU_THR 0.88f
#define STAB_THR 0.95f
#define NMS_THR 0.7f

// Scratch (static device globals -- no runtime allocation)
__device__ int g_hi[NM];
__device__ int g_lo[NM];
__device__ int4 g_box[NM];            // left, top, right, bottom (ints; bottom=-1 => empty)
__device__ float g_gated[NM];
__device__ unsigned g_supmask[NM * 32];

// ---------------------------------------------------------------------------
// Kernel 1: per-mask stats. One block per mask, 8 warps, warp-per-row sweep.
// Per-thread column-bitmask trick: each thread's 8 x-positions are fixed
// across rows, so left/right reduce to one OR per element + end-of-loop
// ffs/clz. No per-row cross-lane reductions at all.
// ---------------------------------------------------------------------------
__global__ __launch_bounds__(256) void stats_kernel(const float* __restrict__ logits) {
    const int n = blockIdx.x;
    const int warp = threadIdx.x >> 5;
    const int lane = threadIdx.x & 31;
    const float* base = logits + (size_t)n * HW;

    int hi = 0, lo = 0;
    int top = HGT, bot = -1;
    unsigned colmask = 0;   // bits 0-3: cols lane*4+c ; bits 4-7: cols lane*4+128+c

    #pragma unroll 4
    for (int r = 0; r < 32; r++) {
        const int y = warp * 32 + r;
        const float4* row = reinterpret_cast<const float4*>(base + (size_t)y * WID);
        float4 a = __ldcs(&row[lane]);
        float4 b = __ldcs(&row[lane + 32]);

        unsigned rm = 0;
        float va[8] = {a.x, a.y, a.z, a.w, b.x, b.y, b.z, b.w};
        #pragma unroll
        for (int c = 0; c < 8; c++) {
            float f = va[c];
            hi += (f > (MASK_THR + STAB_OFF)) ? 1 : 0;
            lo += (f > (MASK_THR - STAB_OFF)) ? 1 : 0;
            rm |= (f > MASK_THR) ? (1u << c) : 0u;
        }
        if (rm) {
            top = min(top, y);
            bot = y;                 // rows ascend -> last positive row wins
            colmask |= rm;
        }
    }

    // Resolve per-thread x extents from the column mask.
    int left = WID, right = -1;
    unsigned lowm = colmask & 0xFu, highm = colmask >> 4;
    if (lowm)  left = lane * 4 + (__ffs(lowm) - 1);
    else if (highm) left = lane * 4 + 128 + (__ffs(highm) - 1);
    if (highm) right = lane * 4 + 128 + (31 - __clz(highm));
    else if (lowm) right = lane * 4 + (31 - __clz(lowm));

    // Warp-level butterfly reduction.
    #pragma unroll
    for (int o = 16; o; o >>= 1) {
        hi   += __shfl_xor_sync(0xffffffffu, hi, o);
        lo   += __shfl_xor_sync(0xffffffffu, lo, o);
        left  = min(left,  __shfl_xor_sync(0xffffffffu, left, o));
        right = max(right, __shfl_xor_sync(0xffffffffu, right, o));
        top   = min(top,   __shfl_xor_sync(0xffffffffu, top, o));
        bot   = max(bot,   __shfl_xor_sync(0xffffffffu, bot, o));
    }

    __shared__ int s[8][6];
    if (lane == 0) {
        s[warp][0] = hi; s[warp][1] = lo;
        s[warp][2] = left; s[warp][3] = right;
        s[warp][4] = top; s[warp][5] = bot;
    }
    __syncthreads();
    if (threadIdx.x == 0) {
        int Hi = 0, Lo = 0, L = WID, R = -1, T = HGT, B = -1;
        #pragma unroll
        for (int w = 0; w < 8; w++) {
            Hi += s[w][0]; Lo += s[w][1];
            L = min(L, s[w][2]); R = max(R, s[w][3]);
            T = min(T, s[w][4]); B = max(B, s[w][5]);
        }
        g_hi[n] = Hi;
        g_lo[n] = Lo;
        g_box[n] = make_int4(L, T, R, B);
    }
}

// ---------------------------------------------------------------------------
// Kernel 2: validity + exact greedy NMS (matches jax argsort-stable ordering),
// writes keep + boxes tail of the output and gated scores for pass 3.
// Single block of 1024 threads.
// ---------------------------------------------------------------------------
__global__ __launch_bounds__(1024) void nms_kernel(const float* __restrict__ iou,
                                                   float* __restrict__ out_tail) {
    const int tid = threadIdx.x;
    __shared__ float s_score[NM];
    __shared__ float4 s_bx[NM];
    __shared__ int s_sorted[NM];
    __shared__ unsigned char s_keep[NM];

    float myiou = iou[tid];
    int4 b = g_box[tid];
    bool nonempty = (b.w >= 0);
    float4 bf = nonempty
        ? make_float4((float)b.x, (float)b.y, (float)b.z, (float)b.w)
        : make_float4(0.f, 0.f, 0.f, 0.f);
    s_bx[tid] = bf;

    float hi = (float)g_hi[tid];
    float lo = fmaxf((float)g_lo[tid], 1.0f);
    float stab = hi / lo;
    bool valid = (myiou > IOU_THR) && (stab >= STAB_THR);
    s_score[tid] = valid ? myiou : -CUDART_INF_F;
    s_keep[tid] = 0;
    int M = __syncthreads_count(valid);

    // Stable rank: score desc, ties -> lower original index first (jnp.argsort).
    if (valid) {
        float si = s_score[tid];
        int r = 0;
        for (int j = 0; j < NM; j++) {
            float sj = s_score[j];
            r += ((sj > si) || (sj == si && j < tid)) ? 1 : 0;
        }
        s_sorted[r] = tid;
    }
    __syncthreads();

    // Suppression bitmask: row i = sorted box i vs all sorted boxes (32 words).
    float4 mb = (tid < M) ? s_bx[s_sorted[tid]] : make_float4(0.f, 0.f, 0.f, 0.f);
    float areaB = fmaxf(mb.z - mb.x, 0.f) * fmaxf(mb.w - mb.y, 0.f);
    for (int i = 0; i < M; i++) {
        float4 ib = s_bx[s_sorted[i]];
        float areaA = fmaxf(ib.z - ib.x, 0.f) * fmaxf(ib.w - ib.y, 0.f);
        float ix = fmaxf(fminf(ib.z, mb.z) - fmaxf(ib.x, mb.x), 0.f);
        float iy = fmaxf(fminf(ib.w, mb.w) - fmaxf(ib.y, mb.y), 0.f);
        float inter = ix * iy;
        float iouv = inter / fmaxf(areaA + areaB - inter, 1e-6f);
        bool bit = (tid < M) && (iouv > NMS_THR);
        unsigned ball = __ballot_sync(0xffffffffu, bit);
        if ((tid & 31) == 0) g_supmask[i * 32 + (tid >> 5)] = ball;
    }
    __syncthreads();  // also fences the global supmask writes block-wide

    // Single-warp greedy over the bitmask (lane l owns removal word l).
    if (tid < 32) {
        unsigned removed = 0;
        for (int i = 0; i < M; i++) {
            unsigned wrd = __shfl_sync(0xffffffffu, removed, i >> 5);
            bool rem = (wrd >> (i & 31)) & 1u;
            if (!rem) {
                removed |= g_supmask[i * 32 + tid];
                if (tid == 0) s_keep[s_sorted[i]] = 1;
            }
        }
    }
    __syncthreads();

    bool kp = (s_keep[tid] != 0);
    g_gated[tid] = kp ? myiou : 0.f;
    out_tail[tid] = kp ? 1.f : 0.f;            // keep[N] as float
    float* ob = out_tail + NM + (size_t)tid * 4;  // boxes [N,4] = (x0,y0,x1,y1)
    ob[0] = bf.x; ob[1] = bf.y; ob[2] = bf.z; ob[3] = bf.w;
}

// ---------------------------------------------------------------------------
// Kernel 3: out = sigmoid(logits) * gated[n]. Suppressed masks are pure
// zero-fill (no load). Grid (4, NM): 4 blocks x 256 threads per mask; each
// thread streams 16 float4 (stcs/ldcs, no L2 pollution, MLP=16).
// ---------------------------------------------------------------------------
__global__ __launch_bounds__(256) void out_kernel(const float* __restrict__ logits,
                                                  float* __restrict__ out) {
    const int n = blockIdx.y;
    const float g = g_gated[n];
    const size_t base = (size_t)n * HW + (size_t)blockIdx.x * (HW / 4);
    float4* o4 = reinterpret_cast<float4*>(out + base);
    const int tid = threadIdx.x;

    if (g == 0.f) {
        const float4 z = make_float4(0.f, 0.f, 0.f, 0.f);
        #pragma unroll
        for (int k = 0; k < 16; k++)
            __stcs(&o4[tid + 256 * k], z);
        return;
    }
    const float4* i4 = reinterpret_cast<const float4*>(logits + base);
    #pragma unroll
    for (int k = 0; k < 16; k++) {
        float4 v = __ldcs(&i4[tid + 256 * k]);
        v.x = __fdividef(g, 1.f + __expf(-v.x));
        v.y = __fdividef(g, 1.f + __expf(-v.y));
        v.z = __fdividef(g, 1.f + __expf(-v.z));
        v.w = __fdividef(g, 1.f + __expf(-v.w));
        __stcs(&o4[tid + 256 * k], v);
    }
}

extern "C" void kernel_launch(void* const* d_in, const int* in_sizes, int n_in,
                              void* d_out, int out_size) {
    const float* logits = (const float*)d_in[0];
    const float* iou = (const float*)d_in[1];
    if (n_in >= 2 && in_sizes[0] == NM && in_sizes[1] == NM * HW) {
        // Defensive against input-order swap.
        logits = (const float*)d_in[1];
        iou = (const float*)d_in[0];
    }
    float* out = (float*)d_out;

    stats_kernel<<<NM, 256>>>(logits);
    nms_kernel<<<1, NM>>>(iou, out + (size_t)NM * HW);
    dim3 grid(4, NM);
    out_kernel<<<grid, 256>>>(logits, out);
}

// round 3
// speedup vs baseline: 1.4516x; 1.3754x over previous
#include <cuda_runtime.h>
#include <math_constants.h>

#define NM 1024
#define HGT 256
#define WID 256
#define HW 65536
#define NPART 4

#define MASK_THR 0.0f
#define STAB_OFF 1.0f
#define IOU_THR 0.88f
#define STAB_THR 0.95f
#define NMS_THR 0.7f

// Scratch (static device globals -- no runtime allocation)
__device__ int g_hiP[NPART * NM];
__device__ int g_loP[NPART * NM];
__device__ int g_LP[NPART * NM];
__device__ int g_RP[NPART * NM];
__device__ int g_TP[NPART * NM];
__device__ int g_BP[NPART * NM];
__device__ float g_gated[NM];
__device__ unsigned g_supmask[NM * 32];   // fallback path only (M > 352)

// ---------------------------------------------------------------------------
// Kernel 1: per-mask stats, 4 partial blocks per mask. Block (part, n) covers
// rows [part*64, part*64+64); each of 8 warps sweeps 8 rows. Column-bitmask
// trick keeps the inner loop to ~3 ALU ops per element with zero cross-lane
// traffic; extents resolved once via ffs/clz at the end.
// ---------------------------------------------------------------------------
__global__ __launch_bounds__(256) void stats_kernel(const float* __restrict__ logits) {
    const int part = blockIdx.x;
    const int n = blockIdx.y;
    const int warp = threadIdx.x >> 5;
    const int lane = threadIdx.x & 31;
    const float* base = logits + (size_t)n * HW;
    const int y0 = part * 64 + warp * 8;

    int hi = 0, lo = 0;
    int top = HGT, bot = -1;
    unsigned colmask = 0;   // bits 0-3: cols lane*4+c ; bits 4-7: cols lane*4+128+c

    #pragma unroll 4
    for (int r = 0; r < 8; r++) {
        const int y = y0 + r;
        const float4* row = reinterpret_cast<const float4*>(base + (size_t)y * WID);
        float4 a = __ldcs(&row[lane]);
        float4 b = __ldcs(&row[lane + 32]);

        unsigned rm = 0;
        float va[8] = {a.x, a.y, a.z, a.w, b.x, b.y, b.z, b.w};
        #pragma unroll
        for (int c = 0; c < 8; c++) {
            float f = va[c];
            hi += (f > (MASK_THR + STAB_OFF)) ? 1 : 0;
            lo += (f > (MASK_THR - STAB_OFF)) ? 1 : 0;
            rm |= (f > MASK_THR) ? (1u << c) : 0u;
        }
        if (rm) {
            top = min(top, y);
            bot = y;                 // rows ascend -> last positive row wins
            colmask |= rm;
        }
    }

    // Resolve per-thread x extents from the column mask.
    int left = WID, right = -1;
    unsigned lowm = colmask & 0xFu, highm = colmask >> 4;
    if (lowm)  left = lane * 4 + (__ffs(lowm) - 1);
    else if (highm) left = lane * 4 + 128 + (__ffs(highm) - 1);
    if (highm) right = lane * 4 + 128 + (31 - __clz(highm));
    else if (lowm) right = lane * 4 + (31 - __clz(lowm));

    // Warp-level butterfly reduction.
    #pragma unroll
    for (int o = 16; o; o >>= 1) {
        hi   += __shfl_xor_sync(0xffffffffu, hi, o);
        lo   += __shfl_xor_sync(0xffffffffu, lo, o);
        left  = min(left,  __shfl_xor_sync(0xffffffffu, left, o));
        right = max(right, __shfl_xor_sync(0xffffffffu, right, o));
        top   = min(top,   __shfl_xor_sync(0xffffffffu, top, o));
        bot   = max(bot,   __shfl_xor_sync(0xffffffffu, bot, o));
    }

    __shared__ int s[8][6];
    if (lane == 0) {
        s[warp][0] = hi; s[warp][1] = lo;
        s[warp][2] = left; s[warp][3] = right;
        s[warp][4] = top; s[warp][5] = bot;
    }
    __syncthreads();
    if (threadIdx.x == 0) {
        int Hi = 0, Lo = 0, L = WID, R = -1, T = HGT, B = -1;
        #pragma unroll
        for (int w = 0; w < 8; w++) {
            Hi += s[w][0]; Lo += s[w][1];
            L = min(L, s[w][2]); R = max(R, s[w][3]);
            T = min(T, s[w][4]); B = max(B, s[w][5]);
        }
        const int o = part * NM + n;
        g_hiP[o] = Hi; g_loP[o] = Lo;
        g_LP[o] = L; g_RP[o] = R; g_TP[o] = T; g_BP[o] = B;
    }
}

// ---------------------------------------------------------------------------
// Kernel 2: combine partials, validity, compacted greedy NMS (exact jax
// argsort-stable ordering). Rank runs over the M~120 valid entries only;
// suppression matrix lives in shared memory (global fallback for M>352).
// ---------------------------------------------------------------------------
__global__ __launch_bounds__(1024) void nms_kernel(const float* __restrict__ iou,
                                                   float* __restrict__ out_tail) {
    const int tid = threadIdx.x;
    const int lane = tid & 31;
    const int wid = tid >> 5;

    __shared__ union {
        struct { float4 bx[NM]; float cs[NM]; int cid[NM]; } p1;      // 24KB
        struct { unsigned sup[4096]; float4 sbx[512]; } p2;           // 24KB (aliases p1)
    } u;
    __shared__ int s_sorted[NM];
    __shared__ unsigned char s_keep[NM];
    __shared__ int s_wcnt[32];

    float myiou = iou[tid];

    // Combine the 4 stats partials.
    int Hi = 0, Lo = 0, L = WID, R = -1, T = HGT, B = -1;
    #pragma unroll
    for (int p = 0; p < NPART; p++) {
        const int o = p * NM + tid;
        Hi += g_hiP[o]; Lo += g_loP[o];
        L = min(L, g_LP[o]); R = max(R, g_RP[o]);
        T = min(T, g_TP[o]); B = max(B, g_BP[o]);
    }
    bool nonempty = (B >= 0);
    float4 bf = nonempty
        ? make_float4((float)L, (float)T, (float)R, (float)B)
        : make_float4(0.f, 0.f, 0.f, 0.f);
    u.p1.bx[tid] = bf;

    float stab = (float)Hi / fmaxf((float)Lo, 1.0f);
    bool valid = (myiou > IOU_THR) && (stab >= STAB_THR);
    s_keep[tid] = 0;

    // Compaction: stable (tid-order) pack of valid entries.
    unsigned bal = __ballot_sync(0xffffffffu, valid);
    if (lane == 0) s_wcnt[wid] = __popc(bal);
    __syncthreads();
    int M = 0, wbase = 0;
    #pragma unroll
    for (int w = 0; w < 32; w++) {
        int cw = s_wcnt[w];
        M += cw;
        if (w < wid) wbase += cw;
    }
    int c = -1;
    if (valid) {
        c = wbase + __popc(bal & ((1u << lane) - 1u));
        u.p1.cs[c] = myiou;
        u.p1.cid[c] = tid;
    }
    __syncthreads();

    // Rank among valid entries only: score desc, ties -> lower original index
    // (compaction is tid-stable, so j<c encodes the tie rule).
    if (valid) {
        int r = 0;
        float si = myiou;
        for (int j = 0; j < M; j++) {
            float sj = u.p1.cs[j];
            r += ((sj > si) || (sj == si && j < c)) ? 1 : 0;
        }
        s_sorted[r] = tid;
    }
    __syncthreads();

    if (M > 0 && M <= 352) {
        const int nwords = (M + 31) >> 5;
        if (tid < M) u.p2.sbx[tid] = u.p1.bx[s_sorted[tid]];  // sbx aliases cs/cid (dead)
        __syncthreads();  // sbx ready; p1.bx reads done before sup overwrites it

        if (tid < nwords * 32) {
            float4 cb = (tid < M) ? u.p2.sbx[tid] : make_float4(0.f, 0.f, 0.f, 0.f);
            float areaB = fmaxf(cb.z - cb.x, 0.f) * fmaxf(cb.w - cb.y, 0.f);
            for (int i = 0; i < M; i++) {
                float4 ib = u.p2.sbx[i];
                float areaA = fmaxf(ib.z - ib.x, 0.f) * fmaxf(ib.w - ib.y, 0.f);
                float ix = fmaxf(fminf(ib.z, cb.z) - fmaxf(ib.x, cb.x), 0.f);
                float iy = fmaxf(fminf(ib.w, cb.w) - fmaxf(ib.y, cb.y), 0.f);
                float inter = ix * iy;
                float iouv = inter / fmaxf(areaA + areaB - inter, 1e-6f);
                bool bit = (tid < M) && (iouv > NMS_THR);
                unsigned bl = __ballot_sync(0xffffffffu, bit);
                if (lane == 0) u.p2.sup[i * nwords + wid] = bl;
            }
        }
        __syncthreads();

        // Single-warp greedy over the shared bitmask.
        if (tid < 32) {
            unsigned removed = 0;
            for (int i = 0; i < M; i++) {
                unsigned w = __shfl_sync(0xffffffffu, removed, i >> 5);
                if (!((w >> (i & 31)) & 1u)) {
                    removed |= (tid < nwords) ? u.p2.sup[i * nwords + tid] : 0u;
                    if (tid == 0) s_keep[s_sorted[i]] = 1;
                }
            }
        }
    } else if (M > 0) {
        // Fallback: global matrix, full 32-word rows (rarely hit).
        float4 mb = (tid < M) ? u.p1.bx[s_sorted[tid]] : make_float4(0.f, 0.f, 0.f, 0.f);
        float areaB = fmaxf(mb.z - mb.x, 0.f) * fmaxf(mb.w - mb.y, 0.f);
        for (int i = 0; i < M; i++) {
            float4 ib = u.p1.bx[s_sorted[i]];
            float areaA = fmaxf(ib.z - ib.x, 0.f) * fmaxf(ib.w - ib.y, 0.f);
            float ix = fmaxf(fminf(ib.z, mb.z) - fmaxf(ib.x, mb.x), 0.f);
            float iy = fmaxf(fminf(ib.w, mb.w) - fmaxf(ib.y, mb.y), 0.f);
            float inter = ix * iy;
            float iouv = inter / fmaxf(areaA + areaB - inter, 1e-6f);
            bool bit = (tid < M) && (iouv > NMS_THR);
            unsigned bl = __ballot_sync(0xffffffffu, bit);
            if (lane == 0) g_supmask[i * 32 + wid] = bl;
        }
        __syncthreads();
        if (tid < 32) {
            unsigned removed = 0;
            for (int i = 0; i < M; i++) {
                unsigned w = __shfl_sync(0xffffffffu, removed, i >> 5);
                if (!((w >> (i & 31)) & 1u)) {
                    removed |= g_supmask[i * 32 + tid];
                    if (tid == 0) s_keep[s_sorted[i]] = 1;
                }
            }
        }
    }
    __syncthreads();

    bool kp = (s_keep[tid] != 0);
    g_gated[tid] = kp ? myiou : 0.f;
    out_tail[tid] = kp ? 1.f : 0.f;              // keep[N] as float
    float* ob = out_tail + NM + (size_t)tid * 4; // boxes [N,4] = (x0,y0,x1,y1)
    ob[0] = bf.x; ob[1] = bf.y; ob[2] = bf.z; ob[3] = bf.w;
}

// ---------------------------------------------------------------------------
// Kernel 3: out = sigmoid(logits) * gated[n]. Suppressed masks are pure
// zero-fill (no load). Grid (4, NM): 4 blocks x 256 threads per mask; each
// thread streams 16 float4 (stcs/ldcs, no L2 pollution, MLP=16).
// ---------------------------------------------------------------------------
__global__ __launch_bounds__(256) void out_kernel(const float* __restrict__ logits,
                                                  float* __restrict__ out) {
    const int n = blockIdx.y;
    const float g = g_gated[n];
    const size_t base = (size_t)n * HW + (size_t)blockIdx.x * (HW / 4);
    float4* o4 = reinterpret_cast<float4*>(out + base);
    const int tid = threadIdx.x;

    if (g == 0.f) {
        const float4 z = make_float4(0.f, 0.f, 0.f, 0.f);
        #pragma unroll
        for (int k = 0; k < 16; k++)
            __stcs(&o4[tid + 256 * k], z);
        return;
    }
    const float4* i4 = reinterpret_cast<const float4*>(logits + base);
    #pragma unroll
    for (int k = 0; k < 16; k++) {
        float4 v = __ldcs(&i4[tid + 256 * k]);
        v.x = __fdividef(g, 1.f + __expf(-v.x));
        v.y = __fdividef(g, 1.f + __expf(-v.y));
        v.z = __fdividef(g, 1.f + __expf(-v.z));
        v.w = __fdividef(g, 1.f + __expf(-v.w));
        __stcs(&o4[tid + 256 * k], v);
    }
}

extern "C" void kernel_launch(void* const* d_in, const int* in_sizes, int n_in,
                              void* d_out, int out_size) {
    const float* logits = (const float*)d_in[0];
    const float* iou = (const float*)d_in[1];
    if (n_in >= 2 && in_sizes[0] == NM && in_sizes[1] == NM * HW) {
        // Defensive against input-order swap.
        logits = (const float*)d_in[1];
        iou = (const float*)d_in[0];
    }
    float* out = (float*)d_out;

    dim3 sgrid(NPART, NM);
    stats_kernel<<<sgrid, 256>>>(logits);
    nms_kernel<<<1, NM>>>(iou, out + (size_t)NM * HW);
    dim3 ogrid(4, NM);
    out_kernel<<<ogrid, 256>>>(logits, out);
}

// round 4
// speedup vs baseline: 1.5677x; 1.0799x over previous
#include <cuda_runtime.h>
#include <math_constants.h>

#define NM 1024
#define HGT 256
#define WID 256
#define HW 65536
#define NPART 4

#define MASK_THR 0.0f
#define STAB_OFF 1.0f
#define IOU_THR 0.88f
#define STAB_THR 0.95f
#define NMS_THR 0.7f

// Scratch (static device globals -- no runtime allocation)
__device__ int g_hiP[NPART * NM];
__device__ int g_loP[NPART * NM];
__device__ int g_LP[NPART * NM];
__device__ int g_RP[NPART * NM];
__device__ int g_TP[NPART * NM];
__device__ int g_BP[NPART * NM];
__device__ float g_gated[NM];
__device__ unsigned g_supmask[NM * 32];   // fallback path only (M > 352)

// ---------------------------------------------------------------------------
// Kernel 1: per-mask stats FUSED with output zero-fill. Block (part, n)
// covers rows [part*64, part*64+64); each of 8 warps sweeps 8 rows. The
// zero-stores to `out` are independent of the loads, so the read and write
// streams overlap on HBM's aggregate bandwidth instead of serializing into
// a read-phase kernel + write-phase kernel. Kept masks (~12%) are
// overwritten by kept_kernel after NMS.
// ---------------------------------------------------------------------------
__global__ __launch_bounds__(256) void stats_zero_kernel(const float* __restrict__ logits,
                                                         float* __restrict__ out) {
    const int part = blockIdx.x;
    const int n = blockIdx.y;
    const int warp = threadIdx.x >> 5;
    const int lane = threadIdx.x & 31;
    const size_t mbase = (size_t)n * HW;
    const float* base = logits + mbase;
    float4* ob = reinterpret_cast<float4*>(out + mbase);
    const int y0 = part * 64 + warp * 8;
    const float4 z = make_float4(0.f, 0.f, 0.f, 0.f);

    int hi = 0, lo = 0;
    int top = HGT, bot = -1;
    unsigned colmask = 0;   // bits 0-3: cols lane*4+c ; bits 4-7: cols lane*4+128+c

    #pragma unroll 4
    for (int r = 0; r < 8; r++) {
        const int y = y0 + r;
        const float4* row = reinterpret_cast<const float4*>(base + (size_t)y * WID);
        float4 a = __ldcs(&row[lane]);
        float4 b = __ldcs(&row[lane + 32]);
        // Independent zero-fill of the same region in out (write stream).
        __stcs(&ob[(size_t)y * (WID / 4) + lane], z);
        __stcs(&ob[(size_t)y * (WID / 4) + lane + 32], z);

        unsigned rm = 0;
        float va[8] = {a.x, a.y, a.z, a.w, b.x, b.y, b.z, b.w};
        #pragma unroll
        for (int c = 0; c < 8; c++) {
            float f = va[c];
            hi += (f > (MASK_THR + STAB_OFF)) ? 1 : 0;
            lo += (f > (MASK_THR - STAB_OFF)) ? 1 : 0;
            rm |= (f > MASK_THR) ? (1u << c) : 0u;
        }
        if (rm) {
            top = min(top, y);
            bot = y;                 // rows ascend -> last positive row wins
            colmask |= rm;
        }
    }

    // Resolve per-thread x extents from the column mask.
    int left = WID, right = -1;
    unsigned lowm = colmask & 0xFu, highm = colmask >> 4;
    if (lowm)  left = lane * 4 + (__ffs(lowm) - 1);
    else if (highm) left = lane * 4 + 128 + (__ffs(highm) - 1);
    if (highm) right = lane * 4 + 128 + (31 - __clz(highm));
    else if (lowm) right = lane * 4 + (31 - __clz(lowm));

    // Warp-level butterfly reduction.
    #pragma unroll
    for (int o = 16; o; o >>= 1) {
        hi   += __shfl_xor_sync(0xffffffffu, hi, o);
        lo   += __shfl_xor_sync(0xffffffffu, lo, o);
        left  = min(left,  __shfl_xor_sync(0xffffffffu, left, o));
        right = max(right, __shfl_xor_sync(0xffffffffu, right, o));
        top   = min(top,   __shfl_xor_sync(0xffffffffu, top, o));
        bot   = max(bot,   __shfl_xor_sync(0xffffffffu, bot, o));
    }

    __shared__ int s[8][6];
    if (lane == 0) {
        s[warp][0] = hi; s[warp][1] = lo;
        s[warp][2] = left; s[warp][3] = right;
        s[warp][4] = top; s[warp][5] = bot;
    }
    __syncthreads();
    if (threadIdx.x == 0) {
        int Hi = 0, Lo = 0, L = WID, R = -1, T = HGT, B = -1;
        #pragma unroll
        for (int w = 0; w < 8; w++) {
            Hi += s[w][0]; Lo += s[w][1];
            L = min(L, s[w][2]); R = max(R, s[w][3]);
            T = min(T, s[w][4]); B = max(B, s[w][5]);
        }
        const int o = part * NM + n;
        g_hiP[o] = Hi; g_loP[o] = Lo;
        g_LP[o] = L; g_RP[o] = R; g_TP[o] = T; g_BP[o] = B;
    }
}

// ---------------------------------------------------------------------------
// Kernel 2: combine partials, validity, compacted greedy NMS (exact jax
// argsort-stable ordering). Rank runs over the M~120 valid entries only;
// suppression matrix lives in shared memory (global fallback for M>352).
// ---------------------------------------------------------------------------
__global__ __launch_bounds__(1024) void nms_kernel(const float* __restrict__ iou,
                                                   float* __restrict__ out_tail) {
    const int tid = threadIdx.x;
    const int lane = tid & 31;
    const int wid = tid >> 5;

    __shared__ union {
        struct { float4 bx[NM]; float cs[NM]; int cid[NM]; } p1;      // 24KB
        struct { unsigned sup[4096]; float4 sbx[512]; } p2;           // 24KB (aliases p1)
    } u;
    __shared__ int s_sorted[NM];
    __shared__ unsigned char s_keep[NM];
    __shared__ int s_wcnt[32];

    float myiou = iou[tid];

    // Combine the 4 stats partials.
    int Hi = 0, Lo = 0, L = WID, R = -1, T = HGT, B = -1;
    #pragma unroll
    for (int p = 0; p < NPART; p++) {
        const int o = p * NM + tid;
        Hi += g_hiP[o]; Lo += g_loP[o];
        L = min(L, g_LP[o]); R = max(R, g_RP[o]);
        T = min(T, g_TP[o]); B = max(B, g_BP[o]);
    }
    bool nonempty = (B >= 0);
    float4 bf = nonempty
        ? make_float4((float)L, (float)T, (float)R, (float)B)
        : make_float4(0.f, 0.f, 0.f, 0.f);
    u.p1.bx[tid] = bf;

    float stab = (float)Hi / fmaxf((float)Lo, 1.0f);
    bool valid = (myiou > IOU_THR) && (stab >= STAB_THR);
    s_keep[tid] = 0;

    // Compaction: stable (tid-order) pack of valid entries.
    unsigned bal = __ballot_sync(0xffffffffu, valid);
    if (lane == 0) s_wcnt[wid] = __popc(bal);
    __syncthreads();
    int M = 0, wbase = 0;
    #pragma unroll
    for (int w = 0; w < 32; w++) {
        int cw = s_wcnt[w];
        M += cw;
        if (w < wid) wbase += cw;
    }
    int c = -1;
    if (valid) {
        c = wbase + __popc(bal & ((1u << lane) - 1u));
        u.p1.cs[c] = myiou;
        u.p1.cid[c] = tid;
    }
    __syncthreads();

    // Rank among valid entries only: score desc, ties -> lower original index
    // (compaction is tid-stable, so j<c encodes the tie rule).
    if (valid) {
        int r = 0;
        float si = myiou;
        for (int j = 0; j < M; j++) {
            float sj = u.p1.cs[j];
            r += ((sj > si) || (sj == si && j < c)) ? 1 : 0;
        }
        s_sorted[r] = tid;
    }
    __syncthreads();

    if (M > 0 && M <= 352) {
        const int nwords = (M + 31) >> 5;
        if (tid < M) u.p2.sbx[tid] = u.p1.bx[s_sorted[tid]];  // sbx aliases cs/cid (dead)
        __syncthreads();  // sbx ready; p1.bx reads done before sup overwrites it

        if (tid < nwords * 32) {
            float4 cb = (tid < M) ? u.p2.sbx[tid] : make_float4(0.f, 0.f, 0.f, 0.f);
            float areaB = fmaxf(cb.z - cb.x, 0.f) * fmaxf(cb.w - cb.y, 0.f);
            for (int i = 0; i < M; i++) {
                float4 ib = u.p2.sbx[i];
                float areaA = fmaxf(ib.z - ib.x, 0.f) * fmaxf(ib.w - ib.y, 0.f);
                float ix = fmaxf(fminf(ib.z, cb.z) - fmaxf(ib.x, cb.x), 0.f);
                float iy = fmaxf(fminf(ib.w, cb.w) - fmaxf(ib.y, cb.y), 0.f);
                float inter = ix * iy;
                float iouv = inter / fmaxf(areaA + areaB - inter, 1e-6f);
                bool bit = (tid < M) && (iouv > NMS_THR);
                unsigned bl = __ballot_sync(0xffffffffu, bit);
                if (lane == 0) u.p2.sup[i * nwords + wid] = bl;
            }
        }
        __syncthreads();

        // Single-warp greedy over the shared bitmask.
        if (tid < 32) {
            unsigned removed = 0;
            for (int i = 0; i < M; i++) {
                unsigned w = __shfl_sync(0xffffffffu, removed, i >> 5);
                if (!((w >> (i & 31)) & 1u)) {
                    removed |= (tid < nwords) ? u.p2.sup[i * nwords + tid] : 0u;
                    if (tid == 0) s_keep[s_sorted[i]] = 1;
                }
            }
        }
    } else if (M > 0) {
        // Fallback: global matrix, full 32-word rows (rarely hit).
        float4 mb = (tid < M) ? u.p1.bx[s_sorted[tid]] : make_float4(0.f, 0.f, 0.f, 0.f);
        float areaB = fmaxf(mb.z - mb.x, 0.f) * fmaxf(mb.w - mb.y, 0.f);
        for (int i = 0; i < M; i++) {
            float4 ib = u.p1.bx[s_sorted[i]];
            float areaA = fmaxf(ib.z - ib.x, 0.f) * fmaxf(ib.w - ib.y, 0.f);
            float ix = fmaxf(fminf(ib.z, mb.z) - fmaxf(ib.x, mb.x), 0.f);
            float iy = fmaxf(fminf(ib.w, mb.w) - fmaxf(ib.y, mb.y), 0.f);
            float inter = ix * iy;
            float iouv = inter / fmaxf(areaA + areaB - inter, 1e-6f);
            bool bit = (tid < M) && (iouv > NMS_THR);
            unsigned bl = __ballot_sync(0xffffffffu, bit);
            if (lane == 0) g_supmask[i * 32 + wid] = bl;
        }
        __syncthreads();
        if (tid < 32) {
            unsigned removed = 0;
            for (int i = 0; i < M; i++) {
                unsigned w = __shfl_sync(0xffffffffu, removed, i >> 5);
                if (!((w >> (i & 31)) & 1u)) {
                    removed |= g_supmask[i * 32 + tid];
                    if (tid == 0) s_keep[s_sorted[i]] = 1;
                }
            }
        }
    }
    __syncthreads();

    bool kp = (s_keep[tid] != 0);
    g_gated[tid] = kp ? myiou : 0.f;
    out_tail[tid] = kp ? 1.f : 0.f;              // keep[N] as float
    float* ob = out_tail + NM + (size_t)tid * 4; // boxes [N,4] = (x0,y0,x1,y1)
    ob[0] = bf.x; ob[1] = bf.y; ob[2] = bf.z; ob[3] = bf.w;
}

// ---------------------------------------------------------------------------
// Kernel 3: rewrite KEPT masks only: out = sigmoid(logits) * gated[n].
// Suppressed masks were already zero-filled by stats_zero_kernel -> those
// blocks exit after one scalar load. Grid (4, NM), 16 float4 per thread.
// ---------------------------------------------------------------------------
__global__ __launch_bounds__(256) void kept_kernel(const float* __restrict__ logits,
                                                   float* __restrict__ out) {
    const int n = blockIdx.y;
    const float g = g_gated[n];
    if (g == 0.f) return;    // already zeroed in pass 1

    const size_t base = (size_t)n * HW + (size_t)blockIdx.x * (HW / 4);
    float4* o4 = reinterpret_cast<float4*>(out + base);
    const float4* i4 = reinterpret_cast<const float4*>(logits + base);
    const int tid = threadIdx.x;
    #pragma unroll
    for (int k = 0; k < 16; k++) {
        float4 v = __ldcs(&i4[tid + 256 * k]);
        v.x = __fdividef(g, 1.f + __expf(-v.x));
        v.y = __fdividef(g, 1.f + __expf(-v.y));
        v.z = __fdividef(g, 1.f + __expf(-v.z));
        v.w = __fdividef(g, 1.f + __expf(-v.w));
        __stcs(&o4[tid + 256 * k], v);
    }
}

extern "C" void kernel_launch(void* const* d_in, const int* in_sizes, int n_in,
                              void* d_out, int out_size) {
    const float* logits = (const float*)d_in[0];
    const float* iou = (const float*)d_in[1];
    if (n_in >= 2 && in_sizes[0] == NM && in_sizes[1] == NM * HW) {
        // Defensive against input-order swap.
        logits = (const float*)d_in[1];
        iou = (const float*)d_in[0];
    }
    float* out = (float*)d_out;

    dim3 sgrid(NPART, NM);
    stats_zero_kernel<<<sgrid, 256>>>(logits, out);
    nms_kernel<<<1, NM>>>(iou, out + (size_t)NM * HW);
    dim3 ogrid(4, NM);
    kept_kernel<<<ogrid, 256>>>(logits, out);
}

// round 5
// speedup vs baseline: 1.6071x; 1.0251x over previous
#include <cuda_runtime.h>
#include <math_constants.h>

#define NM 1024
#define HGT 256
#define WID 256
#define HW 65536
#define NPART 4

#define MASK_THR 0.0f
#define STAB_OFF 1.0f
#define IOU_THR 0.88f
#define STAB_THR 0.95f
#define NMS_THR 0.7f

// Scratch (static device globals -- no runtime allocation)
__device__ int g_hiP[NPART * NM];
__device__ int g_loP[NPART * NM];
__device__ int g_LP[NPART * NM];
__device__ int g_RP[NPART * NM];
__device__ int g_TP[NPART * NM];
__device__ int g_BP[NPART * NM];
__device__ float g_fix[NM];               // 1.0 -> speculation wrong, zero-fill needed
__device__ unsigned g_supmask[NM * 32];   // fallback path only (M > 352)

// ---------------------------------------------------------------------------
// Row sweep, templated on candidate status. Candidates (iou > IOU_THR) get a
// speculative sigmoid(v)*iou written to out -- exactly the final value if the
// mask survives NMS (gated = iou when kept). Non-candidates can never be kept,
// so they get zeros. Either way pass 1 is one read stream + one write stream.
// ---------------------------------------------------------------------------
template<bool CAND>
__device__ __forceinline__ void sweep(const float* __restrict__ base,
                                      float4* __restrict__ ob,
                                      int y0, int lane, float gi,
                                      int& hi, int& lo, int& top, int& bot,
                                      unsigned& colmask) {
    #pragma unroll 4
    for (int r = 0; r < 8; r++) {
        const int y = y0 + r;
        const float4* row = reinterpret_cast<const float4*>(base + (size_t)y * WID);
        float4 a = __ldcs(&row[lane]);
        float4 b = __ldcs(&row[lane + 32]);

        float4 oa, obv;
        if (CAND) {
            oa.x = __fdividef(gi, 1.f + __expf(-a.x));
            oa.y = __fdividef(gi, 1.f + __expf(-a.y));
            oa.z = __fdividef(gi, 1.f + __expf(-a.z));
            oa.w = __fdividef(gi, 1.f + __expf(-a.w));
            obv.x = __fdividef(gi, 1.f + __expf(-b.x));
            obv.y = __fdividef(gi, 1.f + __expf(-b.y));
            obv.z = __fdividef(gi, 1.f + __expf(-b.z));
            obv.w = __fdividef(gi, 1.f + __expf(-b.w));
        } else {
            oa  = make_float4(0.f, 0.f, 0.f, 0.f);
            obv = make_float4(0.f, 0.f, 0.f, 0.f);
        }
        __stcs(&ob[(size_t)y * (WID / 4) + lane], oa);
        __stcs(&ob[(size_t)y * (WID / 4) + lane + 32], obv);

        unsigned rm = 0;
        float va[8] = {a.x, a.y, a.z, a.w, b.x, b.y, b.z, b.w};
        #pragma unroll
        for (int c = 0; c < 8; c++) {
            float f = va[c];
            hi += (f > (MASK_THR + STAB_OFF)) ? 1 : 0;
            lo += (f > (MASK_THR - STAB_OFF)) ? 1 : 0;
            rm |= (f > MASK_THR) ? (1u << c) : 0u;
        }
        if (rm) {
            top = min(top, y);
            bot = y;                 // rows ascend -> last positive row wins
            colmask |= rm;
        }
    }
}

// ---------------------------------------------------------------------------
// Kernel 1: per-mask stats fused with speculative output write. Block
// (part, n) covers rows [part*64, part*64+64); 8 warps x 8 rows each.
// ---------------------------------------------------------------------------
__global__ __launch_bounds__(256) void stats_spec_kernel(const float* __restrict__ logits,
                                                         const float* __restrict__ iou,
                                                         float* __restrict__ out) {
    const int part = blockIdx.x;
    const int n = blockIdx.y;
    const int warp = threadIdx.x >> 5;
    const int lane = threadIdx.x & 31;
    const size_t mbase = (size_t)n * HW;
    const float* base = logits + mbase;
    float4* ob = reinterpret_cast<float4*>(out + mbase);
    const int y0 = part * 64 + warp * 8;
    const float gi = iou[n];

    int hi = 0, lo = 0;
    int top = HGT, bot = -1;
    unsigned colmask = 0;   // bits 0-3: cols lane*4+c ; bits 4-7: cols lane*4+128+c

    if (gi > IOU_THR)
        sweep<true>(base, ob, y0, lane, gi, hi, lo, top, bot, colmask);
    else
        sweep<false>(base, ob, y0, lane, gi, hi, lo, top, bot, colmask);

    // Resolve per-thread x extents from the column mask.
    int left = WID, right = -1;
    unsigned lowm = colmask & 0xFu, highm = colmask >> 4;
    if (lowm)  left = lane * 4 + (__ffs(lowm) - 1);
    else if (highm) left = lane * 4 + 128 + (__ffs(highm) - 1);
    if (highm) right = lane * 4 + 128 + (31 - __clz(highm));
    else if (lowm) right = lane * 4 + (31 - __clz(lowm));

    // Warp-level butterfly reduction.
    #pragma unroll
    for (int o = 16; o; o >>= 1) {
        hi   += __shfl_xor_sync(0xffffffffu, hi, o);
        lo   += __shfl_xor_sync(0xffffffffu, lo, o);
        left  = min(left,  __shfl_xor_sync(0xffffffffu, left, o));
        right = max(right, __shfl_xor_sync(0xffffffffu, right, o));
        top   = min(top,   __shfl_xor_sync(0xffffffffu, top, o));
        bot   = max(bot,   __shfl_xor_sync(0xffffffffu, bot, o));
    }

    __shared__ int s[8][6];
    if (lane == 0) {
        s[warp][0] = hi; s[warp][1] = lo;
        s[warp][2] = left; s[warp][3] = right;
        s[warp][4] = top; s[warp][5] = bot;
    }
    __syncthreads();
    if (threadIdx.x == 0) {
        int Hi = 0, Lo = 0, L = WID, R = -1, T = HGT, B = -1;
        #pragma unroll
        for (int w = 0; w < 8; w++) {
            Hi += s[w][0]; Lo += s[w][1];
            L = min(L, s[w][2]); R = max(R, s[w][3]);
            T = min(T, s[w][4]); B = max(B, s[w][5]);
        }
        const int o = part * NM + n;
        g_hiP[o] = Hi; g_loP[o] = Lo;
        g_LP[o] = L; g_RP[o] = R; g_TP[o] = T; g_BP[o] = B;
    }
}

// ---------------------------------------------------------------------------
// Kernel 2: combine partials, validity, compacted greedy NMS (exact jax
// argsort-stable ordering). Rank runs over the M~120 valid entries only;
// suppression matrix lives in shared memory (global fallback for M>352).
// Emits g_fix = 1 for candidates that were NOT kept (mis-speculation).
// ---------------------------------------------------------------------------
__global__ __launch_bounds__(1024) void nms_kernel(const float* __restrict__ iou,
                                                   float* __restrict__ out_tail) {
    const int tid = threadIdx.x;
    const int lane = tid & 31;
    const int wid = tid >> 5;

    __shared__ union {
        struct { float4 bx[NM]; float cs[NM]; int cid[NM]; } p1;      // 24KB
        struct { unsigned sup[4096]; float4 sbx[512]; } p2;           // 24KB (aliases p1)
    } u;
    __shared__ int s_sorted[NM];
    __shared__ unsigned char s_keep[NM];
    __shared__ int s_wcnt[32];

    float myiou = iou[tid];

    // Combine the 4 stats partials.
    int Hi = 0, Lo = 0, L = WID, R = -1, T = HGT, B = -1;
    #pragma unroll
    for (int p = 0; p < NPART; p++) {
        const int o = p * NM + tid;
        Hi += g_hiP[o]; Lo += g_loP[o];
        L = min(L, g_LP[o]); R = max(R, g_RP[o]);
        T = min(T, g_TP[o]); B = max(B, g_BP[o]);
    }
    bool nonempty = (B >= 0);
    float4 bf = nonempty
        ? make_float4((float)L, (float)T, (float)R, (float)B)
        : make_float4(0.f, 0.f, 0.f, 0.f);
    u.p1.bx[tid] = bf;

    float stab = (float)Hi / fmaxf((float)Lo, 1.0f);
    bool cand = (myiou > IOU_THR);
    bool valid = cand && (stab >= STAB_THR);
    s_keep[tid] = 0;

    // Compaction: stable (tid-order) pack of valid entries.
    unsigned bal = __ballot_sync(0xffffffffu, valid);
    if (lane == 0) s_wcnt[wid] = __popc(bal);
    __syncthreads();
    int M = 0, wbase = 0;
    #pragma unroll
    for (int w = 0; w < 32; w++) {
        int cw = s_wcnt[w];
        M += cw;
        if (w < wid) wbase += cw;
    }
    int c = -1;
    if (valid) {
        c = wbase + __popc(bal & ((1u << lane) - 1u));
        u.p1.cs[c] = myiou;
        u.p1.cid[c] = tid;
    }
    __syncthreads();

    // Rank among valid entries only: score desc, ties -> lower original index
    // (compaction is tid-stable, so j<c encodes the tie rule).
    if (valid) {
        int r = 0;
        float si = myiou;
        for (int j = 0; j < M; j++) {
            float sj = u.p1.cs[j];
            r += ((sj > si) || (sj == si && j < c)) ? 1 : 0;
        }
        s_sorted[r] = tid;
    }
    __syncthreads();

    if (M > 0 && M <= 352) {
        const int nwords = (M + 31) >> 5;
        if (tid < M) u.p2.sbx[tid] = u.p1.bx[s_sorted[tid]];  // sbx aliases cs/cid (dead)
        __syncthreads();  // sbx ready; p1.bx reads done before sup overwrites it

        if (tid < nwords * 32) {
            float4 cb = (tid < M) ? u.p2.sbx[tid] : make_float4(0.f, 0.f, 0.f, 0.f);
            float areaB = fmaxf(cb.z - cb.x, 0.f) * fmaxf(cb.w - cb.y, 0.f);
            for (int i = 0; i < M; i++) {
                float4 ib = u.p2.sbx[i];
                float areaA = fmaxf(ib.z - ib.x, 0.f) * fmaxf(ib.w - ib.y, 0.f);
                float ix = fmaxf(fminf(ib.z, cb.z) - fmaxf(ib.x, cb.x), 0.f);
                float iy = fmaxf(fminf(ib.w, cb.w) - fmaxf(ib.y, cb.y), 0.f);
                float inter = ix * iy;
                float iouv = inter / fmaxf(areaA + areaB - inter, 1e-6f);
                bool bit = (tid < M) && (iouv > NMS_THR);
                unsigned bl = __ballot_sync(0xffffffffu, bit);
                if (lane == 0) u.p2.sup[i * nwords + wid] = bl;
            }
        }
        __syncthreads();

        // Single-warp greedy over the shared bitmask.
        if (tid < 32) {
            unsigned removed = 0;
            for (int i = 0; i < M; i++) {
                unsigned w = __shfl_sync(0xffffffffu, removed, i >> 5);
                if (!((w >> (i & 31)) & 1u)) {
                    removed |= (tid < nwords) ? u.p2.sup[i * nwords + tid] : 0u;
                    if (tid == 0) s_keep[s_sorted[i]] = 1;
                }
            }
        }
    } else if (M > 0) {
        // Fallback: global matrix, full 32-word rows (rarely hit).
        float4 mb = (tid < M) ? u.p1.bx[s_sorted[tid]] : make_float4(0.f, 0.f, 0.f, 0.f);
        float areaB = fmaxf(mb.z - mb.x, 0.f) * fmaxf(mb.w - mb.y, 0.f);
        for (int i = 0; i < M; i++) {
            float4 ib = u.p1.bx[s_sorted[i]];
            float areaA = fmaxf(ib.z - ib.x, 0.f) * fmaxf(ib.w - ib.y, 0.f);
            float ix = fmaxf(fminf(ib.z, mb.z) - fmaxf(ib.x, mb.x), 0.f);
            float iy = fmaxf(fminf(ib.w, mb.w) - fmaxf(ib.y, mb.y), 0.f);
            float inter = ix * iy;
            float iouv = inter / fmaxf(areaA + areaB - inter, 1e-6f);
            bool bit = (tid < M) && (iouv > NMS_THR);
            unsigned bl = __ballot_sync(0xffffffffu, bit);
            if (lane == 0) g_supmask[i * 32 + wid] = bl;
        }
        __syncthreads();
        if (tid < 32) {
            unsigned removed = 0;
            for (int i = 0; i < M; i++) {
                unsigned w = __shfl_sync(0xffffffffu, removed, i >> 5);
                if (!((w >> (i & 31)) & 1u)) {
                    removed |= g_supmask[i * 32 + tid];
                    if (tid == 0) s_keep[s_sorted[i]] = 1;
                }
            }
        }
    }
    __syncthreads();

    bool kp = (s_keep[tid] != 0);
    g_fix[tid] = (cand && !kp) ? 1.f : 0.f;      // mis-speculated -> zero-fill
    out_tail[tid] = kp ? 1.f : 0.f;              // keep[N] as float
    float* ob = out_tail + NM + (size_t)tid * 4; // boxes [N,4] = (x0,y0,x1,y1)
    ob[0] = bf.x; ob[1] = bf.y; ob[2] = bf.z; ob[3] = bf.w;
}

// ---------------------------------------------------------------------------
// Kernel 3: fixup -- zero-fill the few candidate masks that NMS rejected.
// Everything else is already final from pass 1. Grid (4, NM), early exit.
// ---------------------------------------------------------------------------
__global__ __launch_bounds__(256) void fixup_kernel(float* __restrict__ out) {
    const int n = blockIdx.y;
    if (g_fix[n] == 0.f) return;

    const size_t base = (size_t)n * HW + (size_t)blockIdx.x * (HW / 4);
    float4* o4 = reinterpret_cast<float4*>(out + base);
    const int tid = threadIdx.x;
    const float4 z = make_float4(0.f, 0.f, 0.f, 0.f);
    #pragma unroll
    for (int k = 0; k < 16; k++)
        __stcs(&o4[tid + 256 * k], z);
}

extern "C" void kernel_launch(void* const* d_in, const int* in_sizes, int n_in,
                              void* d_out, int out_size) {
    const float* logits = (const float*)d_in[0];
    const float* iou = (const float*)d_in[1];
    if (n_in >= 2 && in_sizes[0] == NM && in_sizes[1] == NM * HW) {
        // Defensive against input-order swap.
        logits = (const float*)d_in[1];
        iou = (const float*)d_in[0];
    }
    float* out = (float*)d_out;

    dim3 sgrid(NPART, NM);
    stats_spec_kernel<<<sgrid, 256>>>(logits, iou, out);
    nms_kernel<<<1, NM>>>(iou, out + (size_t)NM * HW);
    dim3 fgrid(4, NM);
    fixup_kernel<<<fgrid, 256>>>(out);
}

// round 6
// speedup vs baseline: 1.6798x; 1.0452x over previous
#include <cuda_runtime.h>
#include <math_constants.h>

#define NM 1024
#define HGT 256
#define WID 256
#define HW 65536
#define NPART 4
#define FIX_SLOTS 64
#define FIX_PARTS 16

#define MASK_THR 0.0f
#define STAB_OFF 1.0f
#define IOU_THR 0.88f
#define STAB_THR 0.95f
#define NMS_THR 0.7f

// Scratch (static device globals -- no runtime allocation)
__device__ int2 g_cnt[NPART * NM];        // (hi, lo) partials
__device__ int4 g_bxp[NPART * NM];        // (L, R, T, B) partials
__device__ int g_misscnt;                 // # mis-speculated candidate masks
__device__ int g_miss[NM];                // their ids
__device__ unsigned g_supmask[NM * 32];   // fallback path only (M > 352)

// ---------------------------------------------------------------------------
// Row sweep, templated on candidate status. Candidates (iou > IOU_THR) get a
// speculative sigmoid(v)*iou written to out -- exactly the final value if the
// mask survives NMS (gated = iou when kept). Non-candidates can never be kept,
// so they get zeros. Either way pass 1 is one read stream + one write stream.
// ---------------------------------------------------------------------------
template<bool CAND>
__device__ __forceinline__ void sweep(const float* __restrict__ base,
                                      float4* __restrict__ ob,
                                      int y0, int lane, float gi,
                                      int& hi, int& lo, int& top, int& bot,
                                      unsigned& colmask) {
    #pragma unroll 4
    for (int r = 0; r < 8; r++) {
        const int y = y0 + r;
        const float4* row = reinterpret_cast<const float4*>(base + (size_t)y * WID);
        float4 a = __ldcs(&row[lane]);
        float4 b = __ldcs(&row[lane + 32]);

        float4 oa, obv;
        if (CAND) {
            oa.x = __fdividef(gi, 1.f + __expf(-a.x));
            oa.y = __fdividef(gi, 1.f + __expf(-a.y));
            oa.z = __fdividef(gi, 1.f + __expf(-a.z));
            oa.w = __fdividef(gi, 1.f + __expf(-a.w));
            obv.x = __fdividef(gi, 1.f + __expf(-b.x));
            obv.y = __fdividef(gi, 1.f + __expf(-b.y));
            obv.z = __fdividef(gi, 1.f + __expf(-b.z));
            obv.w = __fdividef(gi, 1.f + __expf(-b.w));
        } else {
            oa  = make_float4(0.f, 0.f, 0.f, 0.f);
            obv = make_float4(0.f, 0.f, 0.f, 0.f);
        }
        __stcs(&ob[(size_t)y * (WID / 4) + lane], oa);
        __stcs(&ob[(size_t)y * (WID / 4) + lane + 32], obv);

        unsigned rm = 0;
        float va[8] = {a.x, a.y, a.z, a.w, b.x, b.y, b.z, b.w};
        #pragma unroll
        for (int c = 0; c < 8; c++) {
            float f = va[c];
            hi += (f > (MASK_THR + STAB_OFF)) ? 1 : 0;
            lo += (f > (MASK_THR - STAB_OFF)) ? 1 : 0;
            rm |= (f > MASK_THR) ? (1u << c) : 0u;
        }
        if (rm) {
            top = min(top, y);
            bot = y;                 // rows ascend -> last positive row wins
            colmask |= rm;
        }
    }
}

// ---------------------------------------------------------------------------
// Kernel 1: per-mask stats fused with speculative output write. Block
// (part, n) covers rows [part*64, part*64+64); 8 warps x 8 rows each.
// ---------------------------------------------------------------------------
__global__ __launch_bounds__(256) void stats_spec_kernel(const float* __restrict__ logits,
                                                         const float* __restrict__ iou,
                                                         float* __restrict__ out) {
    const int part = blockIdx.x;
    const int n = blockIdx.y;
    const int warp = threadIdx.x >> 5;
    const int lane = threadIdx.x & 31;
    const size_t mbase = (size_t)n * HW;
    const float* base = logits + mbase;
    float4* ob = reinterpret_cast<float4*>(out + mbase);
    const int y0 = part * 64 + warp * 8;
    const float gi = iou[n];

    int hi = 0, lo = 0;
    int top = HGT, bot = -1;
    unsigned colmask = 0;   // bits 0-3: cols lane*4+c ; bits 4-7: cols lane*4+128+c

    if (gi > IOU_THR)
        sweep<true>(base, ob, y0, lane, gi, hi, lo, top, bot, colmask);
    else
        sweep<false>(base, ob, y0, lane, gi, hi, lo, top, bot, colmask);

    // Resolve per-thread x extents from the column mask.
    int left = WID, right = -1;
    unsigned lowm = colmask & 0xFu, highm = colmask >> 4;
    if (lowm)  left = lane * 4 + (__ffs(lowm) - 1);
    else if (highm) left = lane * 4 + 128 + (__ffs(highm) - 1);
    if (highm) right = lane * 4 + 128 + (31 - __clz(highm));
    else if (lowm) right = lane * 4 + (31 - __clz(lowm));

    // Warp-level butterfly reduction.
    #pragma unroll
    for (int o = 16; o; o >>= 1) {
        hi   += __shfl_xor_sync(0xffffffffu, hi, o);
        lo   += __shfl_xor_sync(0xffffffffu, lo, o);
        left  = min(left,  __shfl_xor_sync(0xffffffffu, left, o));
        right = max(right, __shfl_xor_sync(0xffffffffu, right, o));
        top   = min(top,   __shfl_xor_sync(0xffffffffu, top, o));
        bot   = max(bot,   __shfl_xor_sync(0xffffffffu, bot, o));
    }

    __shared__ int s[8][6];
    if (lane == 0) {
        s[warp][0] = hi; s[warp][1] = lo;
        s[warp][2] = left; s[warp][3] = right;
        s[warp][4] = top; s[warp][5] = bot;
    }
    __syncthreads();
    if (threadIdx.x == 0) {
        int Hi = 0, Lo = 0, L = WID, R = -1, T = HGT, B = -1;
        #pragma unroll
        for (int w = 0; w < 8; w++) {
            Hi += s[w][0]; Lo += s[w][1];
            L = min(L, s[w][2]); R = max(R, s[w][3]);
            T = min(T, s[w][4]); B = max(B, s[w][5]);
        }
        const int o = part * NM + n;
        g_cnt[o] = make_int2(Hi, Lo);
        g_bxp[o] = make_int4(L, R, T, B);
    }
}

// ---------------------------------------------------------------------------
// Kernel 2: combine partials, validity, compacted greedy NMS (exact jax
// argsort-stable ordering). Rank runs over the M~120 valid entries only;
// suppression matrix lives in shared memory (global fallback for M>352).
// Emits a compacted list of mis-speculated candidate masks for the fixup.
// ---------------------------------------------------------------------------
__global__ __launch_bounds__(1024) void nms_kernel(const float* __restrict__ iou,
                                                   float* __restrict__ out_tail) {
    const int tid = threadIdx.x;
    const int lane = tid & 31;
    const int wid = tid >> 5;

    __shared__ union {
        struct { float4 bx[NM]; float cs[NM]; int cid[NM]; } p1;      // 24KB
        struct { unsigned sup[4096]; float4 sbx[512]; } p2;           // 24KB (aliases p1)
    } u;
    __shared__ int s_sorted[NM];
    __shared__ unsigned char s_keep[NM];
    __shared__ int s_wcnt[32];
    __shared__ int s_misscnt;

    float myiou = iou[tid];
    if (tid == 0) s_misscnt = 0;

    // Combine the 4 stats partials (vectorized).
    int Hi = 0, Lo = 0, L = WID, R = -1, T = HGT, B = -1;
    #pragma unroll
    for (int p = 0; p < NPART; p++) {
        const int o = p * NM + tid;
        int2 cl = g_cnt[o];
        int4 bx = g_bxp[o];
        Hi += cl.x; Lo += cl.y;
        L = min(L, bx.x); R = max(R, bx.y);
        T = min(T, bx.z); B = max(B, bx.w);
    }
    bool nonempty = (B >= 0);
    float4 bf = nonempty
        ? make_float4((float)L, (float)T, (float)R, (float)B)
        : make_float4(0.f, 0.f, 0.f, 0.f);
    u.p1.bx[tid] = bf;

    float stab = (float)Hi / fmaxf((float)Lo, 1.0f);
    bool cand = (myiou > IOU_THR);
    bool valid = cand && (stab >= STAB_THR);
    s_keep[tid] = 0;

    // Compaction: stable (tid-order) pack of valid entries.
    unsigned bal = __ballot_sync(0xffffffffu, valid);
    if (lane == 0) s_wcnt[wid] = __popc(bal);
    __syncthreads();
    int M = 0, wbase = 0;
    #pragma unroll
    for (int w = 0; w < 32; w++) {
        int cw = s_wcnt[w];
        M += cw;
        if (w < wid) wbase += cw;
    }
    int c = -1;
    if (valid) {
        c = wbase + __popc(bal & ((1u << lane) - 1u));
        u.p1.cs[c] = myiou;
        u.p1.cid[c] = tid;
    }
    __syncthreads();

    // Rank among valid entries only: score desc, ties -> lower original index
    // (compaction is tid-stable, so j<c encodes the tie rule).
    if (valid) {
        int r = 0;
        float si = myiou;
        for (int j = 0; j < M; j++) {
            float sj = u.p1.cs[j];
            r += ((sj > si) || (sj == si && j < c)) ? 1 : 0;
        }
        s_sorted[r] = tid;
    }
    __syncthreads();

    if (M > 0 && M <= 352) {
        const int nwords = (M + 31) >> 5;
        if (tid < M) u.p2.sbx[tid] = u.p1.bx[s_sorted[tid]];  // sbx aliases cs/cid (dead)
        __syncthreads();  // sbx ready; p1.bx reads done before sup overwrites it

        if (tid < nwords * 32) {
            float4 cb = (tid < M) ? u.p2.sbx[tid] : make_float4(0.f, 0.f, 0.f, 0.f);
            float areaB = fmaxf(cb.z - cb.x, 0.f) * fmaxf(cb.w - cb.y, 0.f);
            for (int i = 0; i < M; i++) {
                float4 ib = u.p2.sbx[i];
                float areaA = fmaxf(ib.z - ib.x, 0.f) * fmaxf(ib.w - ib.y, 0.f);
                float ix = fmaxf(fminf(ib.z, cb.z) - fmaxf(ib.x, cb.x), 0.f);
                float iy = fmaxf(fminf(ib.w, cb.w) - fmaxf(ib.y, cb.y), 0.f);
                float inter = ix * iy;
                float iouv = inter / fmaxf(areaA + areaB - inter, 1e-6f);
                bool bit = (tid < M) && (iouv > NMS_THR);
                unsigned bl = __ballot_sync(0xffffffffu, bit);
                if (lane == 0) u.p2.sup[i * nwords + wid] = bl;
            }
        }
        __syncthreads();

        // Single-warp greedy over the shared bitmask.
        if (tid < 32) {
            unsigned removed = 0;
            for (int i = 0; i < M; i++) {
                unsigned w = __shfl_sync(0xffffffffu, removed, i >> 5);
                if (!((w >> (i & 31)) & 1u)) {
                    removed |= (tid < nwords) ? u.p2.sup[i * nwords + tid] : 0u;
                    if (tid == 0) s_keep[s_sorted[i]] = 1;
                }
            }
        }
    } else if (M > 0) {
        // Fallback: global matrix, full 32-word rows (rarely hit).
        float4 mb = (tid < M) ? u.p1.bx[s_sorted[tid]] : make_float4(0.f, 0.f, 0.f, 0.f);
        float areaB = fmaxf(mb.z - mb.x, 0.f) * fmaxf(mb.w - mb.y, 0.f);
        for (int i = 0; i < M; i++) {
            float4 ib = u.p1.bx[s_sorted[i]];
            float areaA = fmaxf(ib.z - ib.x, 0.f) * fmaxf(ib.w - ib.y, 0.f);
            float ix = fmaxf(fminf(ib.z, mb.z) - fmaxf(ib.x, mb.x), 0.f);
            float iy = fmaxf(fminf(ib.w, mb.w) - fmaxf(ib.y, mb.y), 0.f);
            float inter = ix * iy;
            float iouv = inter / fmaxf(areaA + areaB - inter, 1e-6f);
            bool bit = (tid < M) && (iouv > NMS_THR);
            unsigned bl = __ballot_sync(0xffffffffu, bit);
            if (lane == 0) g_supmask[i * 32 + wid] = bl;
        }
        __syncthreads();
        if (tid < 32) {
            unsigned removed = 0;
            for (int i = 0; i < M; i++) {
                unsigned w = __shfl_sync(0xffffffffu, removed, i >> 5);
                if (!((w >> (i & 31)) & 1u)) {
                    removed |= g_supmask[i * 32 + tid];
                    if (tid == 0) s_keep[s_sorted[i]] = 1;
                }
            }
        }
    }
    __syncthreads();

    bool kp = (s_keep[tid] != 0);
    if (cand && !kp) {
        int slot = atomicAdd(&s_misscnt, 1);
        g_miss[slot] = tid;                      // mis-speculated -> zero-fill
    }
    out_tail[tid] = kp ? 1.f : 0.f;              // keep[N] as float
    float* ob = out_tail + NM + (size_t)tid * 4; // boxes [N,4] = (x0,y0,x1,y1)
    ob[0] = bf.x; ob[1] = bf.y; ob[2] = bf.z; ob[3] = bf.w;
    __syncthreads();
    if (tid == 0) g_misscnt = s_misscnt;
}

// ---------------------------------------------------------------------------
// Kernel 3: fixup -- zero-fill the few candidate masks that NMS rejected.
// Grid-strided over the miss list: (FIX_PARTS, FIX_SLOTS) blocks; slot j
// handles misses j, j+64, ... Each block-iteration writes one 16KB sub-tile.
// ---------------------------------------------------------------------------
__global__ __launch_bounds__(256) void fixup_kernel(float* __restrict__ out) {
    const int cnt = g_misscnt;
    const int tid = threadIdx.x;
    const float4 z = make_float4(0.f, 0.f, 0.f, 0.f);
    for (int j = blockIdx.y; j < cnt; j += FIX_SLOTS) {
        const int n = g_miss[j];
        const size_t base = (size_t)n * HW + (size_t)blockIdx.x * (HW / FIX_PARTS);
        float4* o4 = reinterpret_cast<float4*>(out + base);
        #pragma unroll
        for (int k = 0; k < HW / FIX_PARTS / 4 / 256; k++)
            __stcs(&o4[tid + 256 * k], z);
    }
}

extern "C" void kernel_launch(void* const* d_in, const int* in_sizes, int n_in,
                              void* d_out, int out_size) {
    const float* logits = (const float*)d_in[0];
    const float* iou = (const float*)d_in[1];
    if (n_in >= 2 && in_sizes[0] == NM && in_sizes[1] == NM * HW) {
        // Defensive against input-order swap.
        logits = (const float*)d_in[1];
        iou = (const float*)d_in[0];
    }
    float* out = (float*)d_out;

    dim3 sgrid(NPART, NM);
    stats_spec_kernel<<<sgrid, 256>>>(logits, iou, out);
    nms_kernel<<<1, NM>>>(iou, out + (size_t)NM * HW);
    dim3 fgrid(FIX_PARTS, FIX_SLOTS);
    fixup_kernel<<<fgrid, 256>>>(out);
}